// round 2
// baseline (speedup 1.0000x reference)
#include <cuda_runtime.h>
#include <math.h>

#define BH 32
#define NSEQ 8192
#define DIM 64
#define M 32
#define SCALE 0.125f

#define BPH 16
#define TILE 128
#define RPB (NSEQ / BPH)            /* 512 rows per pass1 block */
#define TPB (RPB / TILE)            /* 4 tiles */

#define SQ_STR 65
#define SV_STR 68
#define SA_STR 33
#define P1_SA 8704                  /* floats: sBuf[0,8704) sA[8704,12928) sKL[12928,14976) */
#define P1_SKL 12928
#define P1_F 14976

__device__ float g_KLt[BH * DIM * M];
__device__ float g_Bs[BH * M * M];
__device__ float g_A[(size_t)BH * NSEQ * M];
__device__ float g_Yp[BH * BPH * M * (DIM + 1)];
__device__ float g_X[BH * M * (DIM + 1)];

typedef unsigned long long u64;
__device__ __forceinline__ u64 pk2(float lo, float hi) {
    u64 r; asm("mov.b64 %0, {%1, %2};" : "=l"(r) : "r"(__float_as_uint(lo)), "r"(__float_as_uint(hi))); return r;
}
__device__ __forceinline__ void upk2(u64 v, float& lo, float& hi) {
    unsigned a, b; asm("mov.b64 {%0, %1}, %2;" : "=r"(a), "=r"(b) : "l"(v));
    lo = __uint_as_float(a); hi = __uint_as_float(b);
}
__device__ __forceinline__ u64 ffma2(u64 a, u64 b, u64 c) {
    u64 d; asm("fma.rn.f32x2 %0, %1, %2, %3;" : "=l"(d) : "l"(a), "l"(b), "l"(c)); return d;
}

__global__ void k_prep(const float* __restrict__ Q, const float* __restrict__ K) {
    int h = blockIdx.x, tid = threadIdx.x;
    __shared__ float sQL[M * 65], sKL[M * 65], sLg[M * 33], sBm[M * 33];
    for (int e = tid; e < M * DIM; e += 128) {
        int m = e >> 6, k = e & 63;
        int idx = (m * (NSEQ - 1)) / (M - 1);
        sKL[m * 65 + k] = K[((size_t)h * NSEQ + idx) * DIM + k] * SCALE;
        sQL[m * 65 + k] = Q[((size_t)h * NSEQ + idx) * DIM + k];
    }
    __syncthreads();
    for (int e = tid; e < M * DIM; e += 128) {
        int m = e & 31, k = e >> 5;
        g_KLt[(h * DIM + k) * M + m] = sKL[m * 65 + k];
    }
    for (int e = tid; e < M * M; e += 128) {
        int i = e >> 5, j = e & 31;
        float s = 0.f;
        #pragma unroll 8
        for (int k = 0; k < DIM; k++) s += sQL[i * 65 + k] * sKL[j * 65 + k];
        sLg[i * 33 + j] = s;
    }
    __syncthreads();
    if (tid < M) {
        int i = tid;
        float mx = -1e30f;
        for (int j = 0; j < M; j++) mx = fmaxf(mx, sLg[i * 33 + j]);
        float s = 0.f;
        for (int j = 0; j < M; j++) { float e2 = __expf(sLg[i * 33 + j] - mx); sBm[i * 33 + j] = e2; s += e2; }
        float r = 1.f / s;
        for (int j = 0; j < M; j++) sBm[i * 33 + j] *= r;
    }
    __syncthreads();
    for (int e = tid; e < M * M; e += 128) {
        int i = e >> 5, j = e & 31;
        g_Bs[h * M * M + e] = 0.5f * (sBm[i * 33 + j] + sBm[j * 33 + i]) + (i == j ? 1e-6f : 0.f);
    }
}

__global__ void __launch_bounds__(128) k_pass1(const float* __restrict__ Q, const float* __restrict__ V) {
    extern __shared__ float sm[];
    float* sBuf = sm;
    float* sA = sm + P1_SA;
    float* sKL = sm + P1_SKL;
    const int h = blockIdx.y, ch = blockIdx.x, tid = threadIdx.x;
    for (int e = tid; e < DIM * M; e += 128) sKL[e] = g_KLt[h * DIM * M + e];
    const int rg = tid >> 2, cg = tid & 3;
    const int ym = tid & 31, yd = (tid >> 5) * 16;
    u64 yacc[8];
    #pragma unroll
    for (int p = 0; p < 8; p++) yacc[p] = 0ull;
    float y1 = 0.f;
    const size_t base = ((size_t)h * NSEQ + (size_t)ch * RPB) * DIM;

    for (int t = 0; t < TPB; t++) {
        __syncthreads();
        const float4* Qg = (const float4*)(Q + base + (size_t)t * TILE * DIM);
        for (int e4 = tid; e4 < TILE * DIM / 4; e4 += 128) {
            float4 v = Qg[e4];
            int n = e4 >> 4, k = (e4 & 15) * 4;
            float* p = sBuf + n * SQ_STR + k;
            p[0] = v.x; p[1] = v.y; p[2] = v.z; p[3] = v.w;
        }
        __syncthreads();
        u64 acc[4][4];
        #pragma unroll
        for (int i = 0; i < 4; i++)
            #pragma unroll
            for (int j = 0; j < 4; j++) acc[i][j] = 0ull;
        const float* klp = sKL + cg * 8;
        const float* qp = sBuf + (rg * 4) * SQ_STR;
        #pragma unroll 4
        for (int k = 0; k < DIM; k++) {
            u64 b0 = *(const u64*)(klp + k * M + 0);
            u64 b1 = *(const u64*)(klp + k * M + 2);
            u64 b2 = *(const u64*)(klp + k * M + 4);
            u64 b3 = *(const u64*)(klp + k * M + 6);
            #pragma unroll
            for (int i = 0; i < 4; i++) {
                float q = qp[i * SQ_STR + k];
                u64 qd = pk2(q, q);
                acc[i][0] = ffma2(qd, b0, acc[i][0]);
                acc[i][1] = ffma2(qd, b1, acc[i][1]);
                acc[i][2] = ffma2(qd, b2, acc[i][2]);
                acc[i][3] = ffma2(qd, b3, acc[i][3]);
            }
        }
        float a[4][8];
        #pragma unroll
        for (int i = 0; i < 4; i++) {
            #pragma unroll
            for (int j = 0; j < 4; j++) upk2(acc[i][j], a[i][2 * j], a[i][2 * j + 1]);
            float mx = a[i][0];
            #pragma unroll
            for (int j = 1; j < 8; j++) mx = fmaxf(mx, a[i][j]);
            mx = fmaxf(mx, __shfl_xor_sync(~0u, mx, 1));
            mx = fmaxf(mx, __shfl_xor_sync(~0u, mx, 2));
            float s = 0.f;
            #pragma unroll
            for (int j = 0; j < 8; j++) { a[i][j] = __expf(a[i][j] - mx); s += a[i][j]; }
            s += __shfl_xor_sync(~0u, s, 1);
            s += __shfl_xor_sync(~0u, s, 2);
            float r = 1.f / s;
            #pragma unroll
            for (int j = 0; j < 8; j++) a[i][j] *= r;
        }
        float* gA = g_A + ((size_t)h * NSEQ + (size_t)ch * RPB + t * TILE) * M;
        #pragma unroll
        for (int i = 0; i < 4; i++) {
            int row = rg * 4 + i;
            #pragma unroll
            for (int j = 0; j < 8; j++) sA[row * SA_STR + cg * 8 + j] = a[i][j];
            *(float4*)&gA[row * M + cg * 8 + 0] = make_float4(a[i][0], a[i][1], a[i][2], a[i][3]);
            *(float4*)&gA[row * M + cg * 8 + 4] = make_float4(a[i][4], a[i][5], a[i][6], a[i][7]);
        }
        __syncthreads();
        const float4* Vg = (const float4*)(V + base + (size_t)t * TILE * DIM);
        for (int e4 = tid; e4 < TILE * DIM / 4; e4 += 128) {
            float4 v = Vg[e4];
            int n = e4 >> 4, k = (e4 & 15) * 4;
            *(float4*)&sBuf[n * SV_STR + k] = v;
        }
        __syncthreads();
        const float* vb = sBuf + yd;
        for (int r = 0; r < TILE; r++) {
            float av = sA[r * SA_STR + ym];
            y1 += av;
            u64 ad = pk2(av, av);
            #pragma unroll
            for (int p = 0; p < 8; p++)
                yacc[p] = ffma2(ad, *(const u64*)(vb + r * SV_STR + 2 * p), yacc[p]);
        }
    }
    float* yp = g_Yp + ((size_t)(h * BPH + ch) * M + ym) * (DIM + 1);
    #pragma unroll
    for (int p = 0; p < 8; p++) {
        float lo, hi; upk2(yacc[p], lo, hi);
        yp[yd + 2 * p] = lo; yp[yd + 2 * p + 1] = hi;
    }
    if (yd == 0) yp[DIM] = y1;
}

__global__ void k_solve() {
    int h = blockIdx.x, tid = threadIdx.x;
    __shared__ float B[M * 33], R[M * 66], f[M];
    __shared__ int piv;
    for (int e = tid; e < M * M; e += 128)
        B[(e >> 5) * 33 + (e & 31)] = g_Bs[h * M * M + e];
    for (int e = tid; e < M * (DIM + 1); e += 128) {
        int m = e / (DIM + 1), c = e % (DIM + 1);
        float s = 0.f;
        for (int q = 0; q < BPH; q++)
            s += g_Yp[((size_t)(h * BPH + q) * M + m) * (DIM + 1) + c];
        R[m * 66 + c] = s;
    }
    __syncthreads();
    for (int k = 0; k < M; k++) {
        if (tid < 32) {
            float v = (tid >= k) ? fabsf(B[tid * 33 + k]) : -1.f;
            int bi = tid;
            #pragma unroll
            for (int o = 16; o; o >>= 1) {
                float ov = __shfl_xor_sync(~0u, v, o);
                int oi = __shfl_xor_sync(~0u, bi, o);
                if (ov > v) { v = ov; bi = oi; }
            }
            if (tid == 0) piv = bi;
        }
        __syncthreads();
        int p = piv;
        if (p != k) {
            for (int c = tid; c < M; c += 128) { float t = B[k * 33 + c]; B[k * 33 + c] = B[p * 33 + c]; B[p * 33 + c] = t; }
            for (int c = tid; c < DIM + 1; c += 128) { float t = R[k * 66 + c]; R[k * 66 + c] = R[p * 66 + c]; R[p * 66 + c] = t; }
        }
        __syncthreads();
        if (tid < 32) f[tid] = B[tid * 33 + k];
        __syncthreads();
        float inv = 1.f / f[k];
        for (int c = tid; c < M; c += 128) B[k * 33 + c] *= inv;
        for (int c = tid; c < DIM + 1; c += 128) R[k * 66 + c] *= inv;
        __syncthreads();
        for (int e = tid; e < M * (M + DIM + 1); e += 128) {
            int i = e / (M + DIM + 1), c = e % (M + DIM + 1);
            if (i == k) continue;
            float fk = f[i];
            if (c < M) B[i * 33 + c] -= fk * B[k * 33 + c];
            else { int cc = c - M; R[i * 66 + cc] -= fk * R[k * 66 + cc]; }
        }
        __syncthreads();
    }
    for (int e = tid; e < M * (DIM + 1); e += 128)
        g_X[h * M * (DIM + 1) + e] = R[(e / (DIM + 1)) * 66 + (e % (DIM + 1))];
}

__global__ void __launch_bounds__(128) k_pass2(float* __restrict__ out) {
    __shared__ float sX[M * 66];
    __shared__ float sA[TILE * SA_STR];
    int h = blockIdx.y, blk = blockIdx.x, tid = threadIdx.x;
    for (int e = tid; e < M * (DIM + 1); e += 128) {
        int m = e / (DIM + 1), c = e % (DIM + 1);
        sX[m * 66 + c] = g_X[h * M * (DIM + 1) + e];
    }
    const float4* Ag = (const float4*)(g_A + ((size_t)h * NSEQ + (size_t)blk * TILE) * M);
    for (int e4 = tid; e4 < TILE * M / 4; e4 += 128) {
        float4 v = Ag[e4];
        int r = e4 >> 3, c = (e4 & 7) * 4;
        float* p = sA + r * SA_STR + c;
        p[0] = v.x; p[1] = v.y; p[2] = v.z; p[3] = v.w;
    }
    __syncthreads();
    int rg = tid >> 2, cg = tid & 3;
    u64 acc[4][8];
    float den[4];
    #pragma unroll
    for (int i = 0; i < 4; i++) { den[i] = 0.f;
        #pragma unroll
        for (int p = 0; p < 8; p++) acc[i][p] = 0ull; }
    const float* xp = sX + cg * 16;
    #pragma unroll 2
    for (int m = 0; m < M; m++) {
        float x1v = sX[m * 66 + 64];
        u64 xv[8];
        #pragma unroll
        for (int p = 0; p < 8; p++) xv[p] = *(const u64*)(xp + m * 66 + 2 * p);
        #pragma unroll
        for (int i = 0; i < 4; i++) {
            float av = sA[(rg * 4 + i) * SA_STR + m];
            den[i] = fmaf(av, x1v, den[i]);
            u64 ad = pk2(av, av);
            #pragma unroll
            for (int p = 0; p < 8; p++) acc[i][p] = ffma2(ad, xv[p], acc[i][p]);
        }
    }
    #pragma unroll
    for (int i = 0; i < 4; i++) {
        int row = blk * TILE + rg * 4 + i;
        float rinv = 1.f / fmaxf(den[i], 1e-20f);
        float v[16];
        #pragma unroll
        for (int p = 0; p < 8; p++) { upk2(acc[i][p], v[2 * p], v[2 * p + 1]); }
        float* op = out + ((size_t)h * NSEQ + row) * DIM + cg * 16;
        *(float4*)&op[0]  = make_float4(v[0] * rinv, v[1] * rinv, v[2] * rinv, v[3] * rinv);
        *(float4*)&op[4]  = make_float4(v[4] * rinv, v[5] * rinv, v[6] * rinv, v[7] * rinv);
        *(float4*)&op[8]  = make_float4(v[8] * rinv, v[9] * rinv, v[10] * rinv, v[11] * rinv);
        *(float4*)&op[12] = make_float4(v[12] * rinv, v[13] * rinv, v[14] * rinv, v[15] * rinv);
    }
}

extern "C" void kernel_launch(void* const* d_in, const int* in_sizes, int n_in,
                              void* d_out, int out_size) {
    const float* Q = (const float*)d_in[0];
    const float* K = (const float*)d_in[1];
    const float* V = (const float*)d_in[2];
    float* out = (float*)d_out;
    cudaFuncSetAttribute(k_pass1, cudaFuncAttributeMaxDynamicSharedMemorySize, P1_F * 4);
    k_prep<<<BH, 128>>>(Q, K);
    k_pass1<<<dim3(BPH, BH), 128, P1_F * 4>>>(Q, V);
    k_solve<<<BH, 128>>>();
    k_pass2<<<dim3(NSEQ / TILE, BH), 128>>>(out);
}